// round 2
// baseline (speedup 1.0000x reference)
#include <cuda_runtime.h>
#include <math.h>
#include <stdint.h>

#define NN      50000
#define NE      800000
#define NG      500
#define DIM     64
#define HID     256
#define NCLS    2000
#define NAT     100
#define TABLE_N 8193
#define CUTOFF  5.0f

#define FLAG_BETA  1
#define FLAG_RELUA 2

// ---------------- scratch (device globals; no allocation allowed) ----------
__device__ float g_node[NN * DIM];
__device__ float g_newnode[NN * DIM];   // also reused as t-buffer
__device__ float g_agg[NN * DIM];
__device__ float g_atom[NN * HID];
__device__ float g_res[NN * HID];
__device__ float g_table[3 * TABLE_N * DIM];
__device__ float g_gsum[NG * HID];
__device__ float g_gcnt[NG];
__device__ float g_gmean[NG * HID];

// ---------------- activations ---------------------------------------------
__device__ __forceinline__ float softplusf(float x) {
    return fmaxf(x, 0.0f) + log1pf(expf(-fabsf(x)));
}
__device__ __forceinline__ float sp2f(float x) {       // 2*softplus(0.5x)
    return 2.0f * softplusf(0.5f * x);
}
__device__ __forceinline__ float sspf(float x) {       // softplus(x) - ln2
    return softplusf(x) - 0.69314718055994531f;
}

// ---------------- tiny utility kernels -------------------------------------
__global__ void zero_kernel(float* __restrict__ p, int n) {
    int i = blockIdx.x * blockDim.x + threadIdx.x;
    if (i < n) p[i] = 0.0f;
}

__global__ void embed_kernel(const int* __restrict__ types,
                             const float* __restrict__ emb,
                             float* __restrict__ node) {
    int i = blockIdx.x * blockDim.x + threadIdx.x;
    if (i >= NN * DIM) return;
    int n = i >> 6;      // /64
    int c = i & 63;
    node[i] = emb[types[n] * DIM + c];
}

// eh(d) table per layer: sp2(sp2(rbf(d)@cf1 + b1)@cf2 + b2)
__global__ void build_table_kernel(const float* __restrict__ cf1_w,  // [3,5,64]
                                   const float* __restrict__ cf1_b,  // [3,64]
                                   const float* __restrict__ cf2_w,  // [3,64,64]
                                   const float* __restrict__ cf2_b,  // [3,64]
                                   float* __restrict__ table) {
    __shared__ float h[DIM];
    int b = blockIdx.x;
    int layer = b / TABLE_N;
    int ent   = b % TABLE_N;
    int j = threadIdx.x;

    const float gap = CUTOFF / 4.0f;                 // linspace(0,5,5) gap = 1.25
    float d = (float)ent * (CUTOFF / (float)(TABLE_N - 1));

    float rbf[5];
#pragma unroll
    for (int r = 0; r < 5; r++) {
        float t = d - (float)r * gap;
        rbf[r] = expf(-(1.0f / gap) * t * t);
    }
    float acc = cf1_b[layer * DIM + j];
#pragma unroll
    for (int r = 0; r < 5; r++)
        acc += rbf[r] * cf1_w[(layer * 5 + r) * DIM + j];
    h[j] = sp2f(acc);
    __syncthreads();

    float acc2 = cf2_b[layer * DIM + j];
    const float* W = cf2_w + layer * DIM * DIM;
#pragma unroll 8
    for (int k = 0; k < DIM; k++)
        acc2 += h[k] * W[k * DIM + j];
    table[(layer * TABLE_N + ent) * DIM + j] = sp2f(acc2);
}

// one warp per edge; each lane handles 2 consecutive floats (float2)
__global__ void edge_kernel(const int* __restrict__ src,
                            const int* __restrict__ dst,
                            const float* __restrict__ dist,
                            const float* __restrict__ newnode,
                            const float* __restrict__ table,   // [TABLE_N,64]
                            float* __restrict__ agg) {
    int idx = blockIdx.x * blockDim.x + threadIdx.x;
    int e = idx >> 5;
    if (e >= NE) return;
    int lane = idx & 31;

    int s = __ldg(src + e);
    int t = __ldg(dst + e);
    float dd = __ldg(dist + e);

    float f = dd * ((float)(TABLE_N - 1) / CUTOFF);
    f = fminf(fmaxf(f, 0.0f), (float)(TABLE_N - 1));
    int i0 = (int)f;
    if (i0 > TABLE_N - 2) i0 = TABLE_N - 2;
    float fr = f - (float)i0;

    const float2* nn = (const float2*)(newnode + (size_t)s * DIM);
    const float2* t0 = (const float2*)(table + (size_t)i0 * DIM);
    const float2* t1 = (const float2*)(table + (size_t)(i0 + 1) * DIM);

    float2 a  = nn[lane];
    float2 u0 = t0[lane];
    float2 u1 = t1[lane];
    float mx = a.x * (u0.x + fr * (u1.x - u0.x));
    float my = a.y * (u0.y + fr * (u1.y - u0.y));

    float* out = agg + (size_t)t * DIM + lane * 2;
    asm volatile("red.global.add.v2.f32 [%0], {%1, %2};"
                 :: "l"(out), "f"(mx), "f"(my) : "memory");
}

// graph pooling: accumulate res rows into per-graph sums
__global__ void pool_kernel(const int* __restrict__ gid,
                            const float* __restrict__ res,
                            float* __restrict__ gsum) {
    int idx = blockIdx.x * blockDim.x + threadIdx.x;   // NN * 128 threads
    if (idx >= NN * (HID / 2)) return;
    int n  = idx >> 7;        // /128
    int c2 = idx & 127;
    int g = __ldg(gid + n);
    const float2 v = ((const float2*)(res + (size_t)n * HID))[c2];
    float* out = gsum + (size_t)g * HID + c2 * 2;
    asm volatile("red.global.add.v2.f32 [%0], {%1, %2};"
                 :: "l"(out), "f"(v.x), "f"(v.y) : "memory");
}

__global__ void count_kernel(const int* __restrict__ gid, float* __restrict__ gcnt) {
    int i = blockIdx.x * blockDim.x + threadIdx.x;
    if (i < NN) atomicAdd(&gcnt[gid[i]], 1.0f);
}

__global__ void mean_kernel(const float* __restrict__ gsum,
                            const float* __restrict__ gcnt,
                            float* __restrict__ gmean) {
    int i = blockIdx.x * blockDim.x + threadIdx.x;
    if (i >= NG * HID) return;
    int g = i >> 8;   // /256
    gmean[i] = gsum[i] / fmaxf(gcnt[g], 1.0f);
}

// ---------------- generic SGEMM: C = act(A@B + bias) [+C] ------------------
// A:[M,K] row-major, B:[K,N] row-major. BM=BN=64, BK=16, 256 threads, 4x4/thread.
// act: 0 none, 1 sp2, 2 ssp.  flags: 1 beta(C+=), 2 relu applied to A on load.
#define BM 64
#define BN 64
#define BK 16

__global__ void sgemm_kernel(const float* __restrict__ A,
                             const float* __restrict__ B,
                             const float* __restrict__ bias,
                             float* __restrict__ C,
                             int M, int N, int K, int act, int flags) {
    __shared__ float As[BK][BM];   // transposed A tile
    __shared__ float Bs[BK][BN];

    int bm = blockIdx.y * BM;
    int bn = blockIdx.x * BN;
    int tid = threadIdx.x;
    int tr = tid >> 4;             // 0..15
    int tc = tid & 15;             // 0..15
    int row0 = tr * 4;
    int col0 = tc * 4;

    float acc[4][4];
#pragma unroll
    for (int i = 0; i < 4; i++)
#pragma unroll
        for (int j = 0; j < 4; j++) acc[i][j] = 0.0f;

    const bool reluA = (flags & FLAG_RELUA) != 0;

    for (int k0 = 0; k0 < K; k0 += BK) {
        // load A tile (BM x BK): 4 elems / thread, row m = tid/4, k = (tid%4)*4
        {
            int m  = tid >> 2;
            int kk = (tid & 3) * 4;
            int gr = bm + m;
#pragma unroll
            for (int i = 0; i < 4; i++) {
                float v = 0.0f;
                if (gr < M) {
                    v = A[(size_t)gr * K + k0 + kk + i];
                    if (reluA) v = fmaxf(v, 0.0f);
                }
                As[kk + i][m] = v;
            }
        }
        // load B tile (BK x BN): k = tid/16, n = (tid%16)*4
        {
            int kk = tid >> 4;
            int n  = (tid & 15) * 4;
#pragma unroll
            for (int i = 0; i < 4; i++) {
                int gc = bn + n + i;
                Bs[kk][n + i] = (gc < N) ? B[(size_t)(k0 + kk) * N + gc] : 0.0f;
            }
        }
        __syncthreads();

#pragma unroll
        for (int kk = 0; kk < BK; kk++) {
            float4 av = ((const float4*)&As[kk][0])[tr];
            float4 bv = ((const float4*)&Bs[kk][0])[tc];
            float a[4] = {av.x, av.y, av.z, av.w};
            float b[4] = {bv.x, bv.y, bv.z, bv.w};
#pragma unroll
            for (int i = 0; i < 4; i++)
#pragma unroll
                for (int j = 0; j < 4; j++)
                    acc[i][j] = fmaf(a[i], b[j], acc[i][j]);
        }
        __syncthreads();
    }

#pragma unroll
    for (int i = 0; i < 4; i++) {
        int r = bm + row0 + i;
        if (r >= M) continue;
#pragma unroll
        for (int j = 0; j < 4; j++) {
            int c = bn + col0 + j;
            if (c >= N) continue;
            float v = acc[i][j];
            if (bias) v += bias[c];
            if (act == 1) v = sp2f(v);
            else if (act == 2) v = sspf(v);
            if (flags & FLAG_BETA) v += C[(size_t)r * N + c];
            C[(size_t)r * N + c] = v;
        }
    }
}

// ---------------- driver ----------------------------------------------------
static inline dim3 gemm_grid(int M, int N) {
    return dim3((N + BN - 1) / BN, (M + BM - 1) / BM);
}

extern "C" void kernel_launch(void* const* d_in, const int* in_sizes, int n_in,
                              void* d_out, int out_size) {
    const int*   node_types = (const int*)  d_in[0];
    const int*   edge_src   = (const int*)  d_in[1];
    const int*   edge_dst   = (const int*)  d_in[2];
    const int*   graph_ids  = (const int*)  d_in[3];
    const float* distance   = (const float*)d_in[4];
    const float* emb        = (const float*)d_in[5];
    const float* conv_w1    = (const float*)d_in[6];
    const float* cf1_w      = (const float*)d_in[7];
    const float* cf1_b      = (const float*)d_in[8];
    const float* cf2_w      = (const float*)d_in[9];
    const float* cf2_b      = (const float*)d_in[10];
    const float* nl2_w      = (const float*)d_in[11];
    const float* nl2_b      = (const float*)d_in[12];
    const float* nl3_w      = (const float*)d_in[13];
    const float* nl3_b      = (const float*)d_in[14];
    const float* d1_w       = (const float*)d_in[15];
    const float* d1_b       = (const float*)d_in[16];
    const float* d2_w       = (const float*)d_in[17];
    const float* d2_b       = (const float*)d_in[18];
    const float* cls_w      = (const float*)d_in[19];
    const float* cls_b      = (const float*)d_in[20];
    const float* ac_w       = (const float*)d_in[21];
    const float* ac_b       = (const float*)d_in[22];
    float* out = (float*)d_out;

    float *node, *newnode, *agg, *atom, *res, *table, *gsum, *gcnt, *gmean;
    cudaGetSymbolAddress((void**)&node,    g_node);
    cudaGetSymbolAddress((void**)&newnode, g_newnode);
    cudaGetSymbolAddress((void**)&agg,     g_agg);
    cudaGetSymbolAddress((void**)&atom,    g_atom);
    cudaGetSymbolAddress((void**)&res,     g_res);
    cudaGetSymbolAddress((void**)&table,   g_table);
    cudaGetSymbolAddress((void**)&gsum,    g_gsum);
    cudaGetSymbolAddress((void**)&gcnt,    g_gcnt);
    cudaGetSymbolAddress((void**)&gmean,   g_gmean);

    // node = emb[node_types]
    embed_kernel<<<(NN * DIM + 255) / 256, 256>>>(node_types, emb, node);

    // per-layer eh(d) lookup tables
    build_table_kernel<<<3 * TABLE_N, DIM>>>(cf1_w, cf1_b, cf2_w, cf2_b, table);

    dim3 g64 = gemm_grid(NN, DIM);
    for (int l = 0; l < 3; l++) {
        // newnode = node @ w1
        sgemm_kernel<<<g64, 256>>>(node, conv_w1 + (size_t)l * DIM * DIM,
                                   nullptr, newnode, NN, DIM, DIM, 0, 0);
        // agg = 0
        zero_kernel<<<(NN * DIM + 255) / 256, 256>>>(agg, NN * DIM);
        // agg[dst] += newnode[src] * eh(d)
        edge_kernel<<<(NE * 32 + 255) / 256, 256>>>(
            edge_src, edge_dst, distance, newnode,
            table + (size_t)l * TABLE_N * DIM, agg);
        // t = sp2(agg @ nl2 + b2)   (reuse newnode as t)
        sgemm_kernel<<<g64, 256>>>(agg, nl2_w + (size_t)l * DIM * DIM,
                                   nl2_b + l * DIM, newnode, NN, DIM, DIM, 1, 0);
        // node += t @ nl3 + b3
        sgemm_kernel<<<g64, 256>>>(newnode, nl3_w + (size_t)l * DIM * DIM,
                                   nl3_b + l * DIM, node, NN, DIM, DIM, 0, FLAG_BETA);
    }

    // atom = ssp(node @ d1 + b)
    sgemm_kernel<<<gemm_grid(NN, HID), 256>>>(node, d1_w, d1_b, atom,
                                              NN, HID, DIM, 2, 0);
    // res = atom @ d2 + b
    sgemm_kernel<<<gemm_grid(NN, HID), 256>>>(atom, d2_w, d2_b, res,
                                              NN, HID, HID, 0, 0);
    // atoms_preds = relu(res) @ ac + b   -> out[0 : NN*100]
    sgemm_kernel<<<gemm_grid(NN, NAT), 256>>>(res, ac_w, ac_b, out,
                                              NN, NAT, HID, 0, FLAG_RELUA);

    // graph pooling
    zero_kernel<<<(NG * HID + 255) / 256, 256>>>(gsum, NG * HID);
    zero_kernel<<<(NG + 255) / 256, 256>>>(gcnt, NG);
    pool_kernel<<<(NN * (HID / 2) + 255) / 256, 256>>>(graph_ids, res, gsum);
    count_kernel<<<(NN + 255) / 256, 256>>>(graph_ids, gcnt);
    mean_kernel<<<(NG * HID + 255) / 256, 256>>>(gsum, gcnt, gmean);

    // cls_preds = gmean @ cls_w + b -> out[NN*100 : ]
    sgemm_kernel<<<gemm_grid(NG, NCLS), 256>>>(gmean, cls_w, cls_b,
                                               out + (size_t)NN * NAT,
                                               NG, NCLS, HID, 0, 0);
}

// round 3
// speedup vs baseline: 1.2995x; 1.2995x over previous
#include <cuda_runtime.h>
#include <math.h>
#include <stdint.h>

#define NN      50000
#define NE      800000
#define NG      500
#define DIM     64
#define HID     256
#define NCLS    2000
#define NAT     100
#define TABLE_N 8193
#define CUTOFF  5.0f

#define FLAG_BETA  1
#define FLAG_RELUA 2

// ---------------- scratch (device globals; no allocation allowed) ----------
__device__ float g_node[NN * DIM];
__device__ float g_newnode[NN * DIM];   // also reused as t-buffer
__device__ float g_agg[NN * DIM];
__device__ float g_atom[NN * HID];
__device__ float g_res[NN * HID];
__device__ float g_table[3 * TABLE_N * DIM];
__device__ float g_gsum[NG * HID];
__device__ float g_gcnt[NG];
__device__ float g_gmean[NG * HID];

// ---------------- activations ---------------------------------------------
__device__ __forceinline__ float softplusf(float x) {
    return fmaxf(x, 0.0f) + log1pf(expf(-fabsf(x)));
}
__device__ __forceinline__ float sp2f(float x) {       // 2*softplus(0.5x)
    return 2.0f * softplusf(0.5f * x);
}
__device__ __forceinline__ float sspf(float x) {       // softplus(x) - ln2
    return softplusf(x) - 0.69314718055994531f;
}

// ---------------- f32x2 packed math ----------------------------------------
__device__ __forceinline__ uint64_t pack2(float lo, float hi) {
    uint64_t r;
    asm("mov.b64 %0, {%1, %2};" : "=l"(r) : "f"(lo), "f"(hi));
    return r;
}
__device__ __forceinline__ uint64_t dup2(float v) {
    uint64_t r;
    asm("mov.b64 %0, {%1, %1};" : "=l"(r) : "f"(v));
    return r;
}
__device__ __forceinline__ void ffma2(uint64_t& d, uint64_t a, uint64_t b) {
    asm("fma.rn.f32x2 %0, %1, %2, %0;" : "+l"(d) : "l"(a), "l"(b));
}
__device__ __forceinline__ void unpack2(uint64_t v, float& lo, float& hi) {
    asm("mov.b64 {%0, %1}, %2;" : "=f"(lo), "=f"(hi) : "l"(v));
}

// ---------------- tiny utility kernels -------------------------------------
__global__ void zero_kernel(float* __restrict__ p, int n) {
    int i = blockIdx.x * blockDim.x + threadIdx.x;
    if (i < n) p[i] = 0.0f;
}

__global__ void embed_kernel(const int* __restrict__ types,
                             const float* __restrict__ emb,
                             float* __restrict__ node) {
    int i = blockIdx.x * blockDim.x + threadIdx.x;
    if (i >= NN * DIM) return;
    int n = i >> 6;      // /64
    int c = i & 63;
    node[i] = emb[types[n] * DIM + c];
}

// eh(d) table per layer: sp2(sp2(rbf(d)@cf1 + b1)@cf2 + b2)
__global__ void build_table_kernel(const float* __restrict__ cf1_w,  // [3,5,64]
                                   const float* __restrict__ cf1_b,  // [3,64]
                                   const float* __restrict__ cf2_w,  // [3,64,64]
                                   const float* __restrict__ cf2_b,  // [3,64]
                                   float* __restrict__ table) {
    __shared__ float h[DIM];
    int b = blockIdx.x;
    int layer = b / TABLE_N;
    int ent   = b % TABLE_N;
    int j = threadIdx.x;

    const float gap = CUTOFF / 4.0f;                 // linspace(0,5,5) gap = 1.25
    float d = (float)ent * (CUTOFF / (float)(TABLE_N - 1));

    float rbf[5];
#pragma unroll
    for (int r = 0; r < 5; r++) {
        float t = d - (float)r * gap;
        rbf[r] = expf(-(1.0f / gap) * t * t);
    }
    float acc = cf1_b[layer * DIM + j];
#pragma unroll
    for (int r = 0; r < 5; r++)
        acc += rbf[r] * cf1_w[(layer * 5 + r) * DIM + j];
    h[j] = sp2f(acc);
    __syncthreads();

    float acc2 = cf2_b[layer * DIM + j];
    const float* W = cf2_w + layer * DIM * DIM;
#pragma unroll 8
    for (int k = 0; k < DIM; k++)
        acc2 += h[k] * W[k * DIM + j];
    table[(layer * TABLE_N + ent) * DIM + j] = sp2f(acc2);
}

// one warp per edge; each lane handles 2 consecutive floats (float2)
__global__ void edge_kernel(const int* __restrict__ src,
                            const int* __restrict__ dst,
                            const float* __restrict__ dist,
                            const float* __restrict__ newnode,
                            const float* __restrict__ table,   // [TABLE_N,64]
                            float* __restrict__ agg) {
    int idx = blockIdx.x * blockDim.x + threadIdx.x;
    int e = idx >> 5;
    if (e >= NE) return;
    int lane = idx & 31;

    int s = __ldg(src + e);
    int t = __ldg(dst + e);
    float dd = __ldg(dist + e);

    float f = dd * ((float)(TABLE_N - 1) / CUTOFF);
    f = fminf(fmaxf(f, 0.0f), (float)(TABLE_N - 1));
    int i0 = (int)f;
    if (i0 > TABLE_N - 2) i0 = TABLE_N - 2;
    float fr = f - (float)i0;

    const float2* nn = (const float2*)(newnode + (size_t)s * DIM);
    const float2* t0 = (const float2*)(table + (size_t)i0 * DIM);
    const float2* t1 = (const float2*)(table + (size_t)(i0 + 1) * DIM);

    float2 a  = nn[lane];
    float2 u0 = t0[lane];
    float2 u1 = t1[lane];
    float mx = a.x * (u0.x + fr * (u1.x - u0.x));
    float my = a.y * (u0.y + fr * (u1.y - u0.y));

    float* out = agg + (size_t)t * DIM + lane * 2;
    asm volatile("red.global.add.v2.f32 [%0], {%1, %2};"
                 :: "l"(out), "f"(mx), "f"(my) : "memory");
}

// graph pooling: accumulate res rows into per-graph sums
__global__ void pool_kernel(const int* __restrict__ gid,
                            const float* __restrict__ res,
                            float* __restrict__ gsum) {
    int idx = blockIdx.x * blockDim.x + threadIdx.x;   // NN * 128 threads
    if (idx >= NN * (HID / 2)) return;
    int n  = idx >> 7;        // /128
    int c2 = idx & 127;
    int g = __ldg(gid + n);
    const float2 v = ((const float2*)(res + (size_t)n * HID))[c2];
    float* out = gsum + (size_t)g * HID + c2 * 2;
    asm volatile("red.global.add.v2.f32 [%0], {%1, %2};"
                 :: "l"(out), "f"(v.x), "f"(v.y) : "memory");
}

__global__ void count_kernel(const int* __restrict__ gid, float* __restrict__ gcnt) {
    int i = blockIdx.x * blockDim.x + threadIdx.x;
    if (i < NN) atomicAdd(&gcnt[gid[i]], 1.0f);
}

__global__ void mean_kernel(const float* __restrict__ gsum,
                            const float* __restrict__ gcnt,
                            float* __restrict__ gmean) {
    int i = blockIdx.x * blockDim.x + threadIdx.x;
    if (i >= NG * HID) return;
    int g = i >> 8;   // /256
    gmean[i] = gsum[i] / fmaxf(gcnt[g], 1.0f);
}

// ---------------- SGEMM with packed f32x2 FMAs ------------------------------
// C = act(A@B + bias) [+C].  A:[M,K] rm, B:[K,N] rm.
// BM=128, BN=64, BK=16, 256 threads (32x8), microtile 4 rows x 8 cols (4 f32x2 pairs).
// act: 0 none, 1 sp2, 2 ssp.  flags: 1 beta(C+=), 2 relu applied to A on load.
#define BM 128
#define BN 64
#define BK 16

__global__ __launch_bounds__(256)
void sgemm_kernel(const float* __restrict__ A,
                  const float* __restrict__ B,
                  const float* __restrict__ bias,
                  float* __restrict__ C,
                  int M, int N, int K, int act, int flags) {
    __shared__ float As[BK][BM];   // transposed A tile
    __shared__ float Bs[BK][BN];

    int bm = blockIdx.y * BM;
    int bn = blockIdx.x * BN;
    int tid = threadIdx.x;
    int tr = tid >> 3;             // 0..31  (rows)
    int tc = tid & 7;              // 0..7   (col groups of 8)
    int row0 = tr * 4;
    int col0 = tc * 8;

    uint64_t acc[4][4];            // 4 rows x 4 f32x2 pairs (8 cols)
#pragma unroll
    for (int i = 0; i < 4; i++)
#pragma unroll
        for (int j = 0; j < 4; j++) acc[i][j] = 0ull;

    const bool reluA = (flags & FLAG_RELUA) != 0;

    for (int k0 = 0; k0 < K; k0 += BK) {
        // load A tile (BM x BK = 2048 floats): 2 float4 per thread, transposed store
#pragma unroll
        for (int q = 0; q < 2; q++) {
            int lin = tid * 2 + q;          // 0..511 float4 slots
            int m   = lin >> 2;             // 0..127
            int ks  = (lin & 3) * 4;        // 0,4,8,12
            int gr  = bm + m;
            float4 v = make_float4(0.f, 0.f, 0.f, 0.f);
            if (gr < M)
                v = *(const float4*)(A + (size_t)gr * K + k0 + ks);
            if (reluA) {
                v.x = fmaxf(v.x, 0.f); v.y = fmaxf(v.y, 0.f);
                v.z = fmaxf(v.z, 0.f); v.w = fmaxf(v.w, 0.f);
            }
            As[ks + 0][m] = v.x;
            As[ks + 1][m] = v.y;
            As[ks + 2][m] = v.z;
            As[ks + 3][m] = v.w;
        }
        // load B tile (BK x BN = 1024 floats): 1 float4 per thread
        {
            int kk = tid >> 4;              // 0..15
            int n  = (tid & 15) * 4;        // 0..60
            float4 v;
            int gc = bn + n;
            if (gc + 3 < N) {
                v = *(const float4*)(B + (size_t)(k0 + kk) * N + gc);
            } else {
                v.x = (gc + 0 < N) ? B[(size_t)(k0 + kk) * N + gc + 0] : 0.f;
                v.y = (gc + 1 < N) ? B[(size_t)(k0 + kk) * N + gc + 1] : 0.f;
                v.z = (gc + 2 < N) ? B[(size_t)(k0 + kk) * N + gc + 2] : 0.f;
                v.w = (gc + 3 < N) ? B[(size_t)(k0 + kk) * N + gc + 3] : 0.f;
            }
            *(float4*)&Bs[kk][n] = v;
        }
        __syncthreads();

#pragma unroll
        for (int kk = 0; kk < BK; kk++) {
            float4 av  = *(const float4*)&As[kk][row0];
            float4 bv0 = *(const float4*)&Bs[kk][col0];
            float4 bv1 = *(const float4*)&Bs[kk][col0 + 4];
            uint64_t bb[4];
            bb[0] = pack2(bv0.x, bv0.y);
            bb[1] = pack2(bv0.z, bv0.w);
            bb[2] = pack2(bv1.x, bv1.y);
            bb[3] = pack2(bv1.z, bv1.w);
            uint64_t aa;
            aa = dup2(av.x);
            ffma2(acc[0][0], aa, bb[0]); ffma2(acc[0][1], aa, bb[1]);
            ffma2(acc[0][2], aa, bb[2]); ffma2(acc[0][3], aa, bb[3]);
            aa = dup2(av.y);
            ffma2(acc[1][0], aa, bb[0]); ffma2(acc[1][1], aa, bb[1]);
            ffma2(acc[1][2], aa, bb[2]); ffma2(acc[1][3], aa, bb[3]);
            aa = dup2(av.z);
            ffma2(acc[2][0], aa, bb[0]); ffma2(acc[2][1], aa, bb[1]);
            ffma2(acc[2][2], aa, bb[2]); ffma2(acc[2][3], aa, bb[3]);
            aa = dup2(av.w);
            ffma2(acc[3][0], aa, bb[0]); ffma2(acc[3][1], aa, bb[1]);
            ffma2(acc[3][2], aa, bb[2]); ffma2(acc[3][3], aa, bb[3]);
        }
        __syncthreads();
    }

#pragma unroll
    for (int i = 0; i < 4; i++) {
        int r = bm + row0 + i;
        if (r >= M) continue;
        float vals[8];
#pragma unroll
        for (int j = 0; j < 4; j++)
            unpack2(acc[i][j], vals[j * 2], vals[j * 2 + 1]);
#pragma unroll
        for (int j = 0; j < 8; j++) {
            int c = bn + col0 + j;
            if (c >= N) continue;
            float v = vals[j];
            if (bias) v += bias[c];
            if (act == 1) v = sp2f(v);
            else if (act == 2) v = sspf(v);
            if (flags & FLAG_BETA) v += C[(size_t)r * N + c];
            C[(size_t)r * N + c] = v;
        }
    }
}

// ---------------- driver ----------------------------------------------------
static inline dim3 gemm_grid(int M, int N) {
    return dim3((N + BN - 1) / BN, (M + BM - 1) / BM);
}

extern "C" void kernel_launch(void* const* d_in, const int* in_sizes, int n_in,
                              void* d_out, int out_size) {
    const int*   node_types = (const int*)  d_in[0];
    const int*   edge_src   = (const int*)  d_in[1];
    const int*   edge_dst   = (const int*)  d_in[2];
    const int*   graph_ids  = (const int*)  d_in[3];
    const float* distance   = (const float*)d_in[4];
    const float* emb        = (const float*)d_in[5];
    const float* conv_w1    = (const float*)d_in[6];
    const float* cf1_w      = (const float*)d_in[7];
    const float* cf1_b      = (const float*)d_in[8];
    const float* cf2_w      = (const float*)d_in[9];
    const float* cf2_b      = (const float*)d_in[10];
    const float* nl2_w      = (const float*)d_in[11];
    const float* nl2_b      = (const float*)d_in[12];
    const float* nl3_w      = (const float*)d_in[13];
    const float* nl3_b      = (const float*)d_in[14];
    const float* d1_w       = (const float*)d_in[15];
    const float* d1_b       = (const float*)d_in[16];
    const float* d2_w       = (const float*)d_in[17];
    const float* d2_b       = (const float*)d_in[18];
    const float* cls_w      = (const float*)d_in[19];
    const float* cls_b      = (const float*)d_in[20];
    const float* ac_w       = (const float*)d_in[21];
    const float* ac_b       = (const float*)d_in[22];
    float* out = (float*)d_out;

    float *node, *newnode, *agg, *atom, *res, *table, *gsum, *gcnt, *gmean;
    cudaGetSymbolAddress((void**)&node,    g_node);
    cudaGetSymbolAddress((void**)&newnode, g_newnode);
    cudaGetSymbolAddress((void**)&agg,     g_agg);
    cudaGetSymbolAddress((void**)&atom,    g_atom);
    cudaGetSymbolAddress((void**)&res,     g_res);
    cudaGetSymbolAddress((void**)&table,   g_table);
    cudaGetSymbolAddress((void**)&gsum,    g_gsum);
    cudaGetSymbolAddress((void**)&gcnt,    g_gcnt);
    cudaGetSymbolAddress((void**)&gmean,   g_gmean);

    // node = emb[node_types]
    embed_kernel<<<(NN * DIM + 255) / 256, 256>>>(node_types, emb, node);

    // per-layer eh(d) lookup tables
    build_table_kernel<<<3 * TABLE_N, DIM>>>(cf1_w, cf1_b, cf2_w, cf2_b, table);

    dim3 g64 = gemm_grid(NN, DIM);
    for (int l = 0; l < 3; l++) {
        // newnode = node @ w1
        sgemm_kernel<<<g64, 256>>>(node, conv_w1 + (size_t)l * DIM * DIM,
                                   nullptr, newnode, NN, DIM, DIM, 0, 0);
        // agg = 0
        zero_kernel<<<(NN * DIM + 255) / 256, 256>>>(agg, NN * DIM);
        // agg[dst] += newnode[src] * eh(d)
        edge_kernel<<<(NE * 32 + 255) / 256, 256>>>(
            edge_src, edge_dst, distance, newnode,
            table + (size_t)l * TABLE_N * DIM, agg);
        // t = sp2(agg @ nl2 + b2)   (reuse newnode as t)
        sgemm_kernel<<<g64, 256>>>(agg, nl2_w + (size_t)l * DIM * DIM,
                                   nl2_b + l * DIM, newnode, NN, DIM, DIM, 1, 0);
        // node += t @ nl3 + b3
        sgemm_kernel<<<g64, 256>>>(newnode, nl3_w + (size_t)l * DIM * DIM,
                                   nl3_b + l * DIM, node, NN, DIM, DIM, 0, FLAG_BETA);
    }

    // atom = ssp(node @ d1 + b)
    sgemm_kernel<<<gemm_grid(NN, HID), 256>>>(node, d1_w, d1_b, atom,
                                              NN, HID, DIM, 2, 0);
    // res = atom @ d2 + b
    sgemm_kernel<<<gemm_grid(NN, HID), 256>>>(atom, d2_w, d2_b, res,
                                              NN, HID, HID, 0, 0);
    // atoms_preds = relu(res) @ ac + b   -> out[0 : NN*100]
    sgemm_kernel<<<gemm_grid(NN, NAT), 256>>>(res, ac_w, ac_b, out,
                                              NN, NAT, HID, 0, FLAG_RELUA);

    // graph pooling
    zero_kernel<<<(NG * HID + 255) / 256, 256>>>(gsum, NG * HID);
    zero_kernel<<<(NG + 255) / 256, 256>>>(gcnt, NG);
    pool_kernel<<<(NN * (HID / 2) + 255) / 256, 256>>>(graph_ids, res, gsum);
    count_kernel<<<(NN + 255) / 256, 256>>>(graph_ids, gcnt);
    mean_kernel<<<(NG * HID + 255) / 256, 256>>>(gsum, gcnt, gmean);

    // cls_preds = gmean @ cls_w + b -> out[NN*100 : ]
    sgemm_kernel<<<gemm_grid(NG, NCLS), 256>>>(gmean, cls_w, cls_b,
                                               out + (size_t)NN * NAT,
                                               NG, NCLS, HID, 0, 0);
}

// round 4
// speedup vs baseline: 1.3814x; 1.0630x over previous
#include <cuda_runtime.h>
#include <math.h>
#include <stdint.h>

#define NN      50000
#define NE      800000
#define NG      500
#define DIM     64
#define HID     256
#define NCLS    2000
#define NAT     100
#define TABLE_N 8193
#define CUTOFF  5.0f

#define FLAG_BETA  1
#define FLAG_RELUA 2

// ---------------- scratch (device globals; no allocation allowed) ----------
__device__ float g_node[NN * DIM];
__device__ float g_newnode[NN * DIM];   // also reused as t-buffer
__device__ float g_agg[NN * DIM];
__device__ float g_atom[NN * HID];
__device__ float g_res[NN * HID];
__device__ float g_table[3 * TABLE_N * DIM];
__device__ float g_gsum[NG * HID];
__device__ float g_gcnt[NG];
__device__ float g_gmean[NG * HID];

// ---------------- activations ---------------------------------------------
__device__ __forceinline__ float softplusf(float x) {
    return fmaxf(x, 0.0f) + log1pf(expf(-fabsf(x)));
}
__device__ __forceinline__ float sp2f(float x) {       // 2*softplus(0.5x)
    return 2.0f * softplusf(0.5f * x);
}
__device__ __forceinline__ float sspf(float x) {       // softplus(x) - ln2
    return softplusf(x) - 0.69314718055994531f;
}

// ---------------- f32x2 packed math ----------------------------------------
__device__ __forceinline__ uint64_t pack2(float lo, float hi) {
    uint64_t r;
    asm("mov.b64 %0, {%1, %2};" : "=l"(r) : "f"(lo), "f"(hi));
    return r;
}
__device__ __forceinline__ uint64_t dup2(float v) {
    uint64_t r;
    asm("mov.b64 %0, {%1, %1};" : "=l"(r) : "f"(v));
    return r;
}
__device__ __forceinline__ void ffma2(uint64_t& d, uint64_t a, uint64_t b) {
    asm("fma.rn.f32x2 %0, %1, %2, %0;" : "+l"(d) : "l"(a), "l"(b));
}
__device__ __forceinline__ void unpack2(uint64_t v, float& lo, float& hi) {
    asm("mov.b64 {%0, %1}, %2;" : "=f"(lo), "=f"(hi) : "l"(v));
}

// ---------------- tiny utility kernels -------------------------------------
__global__ void zero_kernel(float* __restrict__ p, int n) {
    int i = blockIdx.x * blockDim.x + threadIdx.x;
    if (i < n) p[i] = 0.0f;
}

__global__ void embed_kernel(const int* __restrict__ types,
                             const float* __restrict__ emb,
                             float* __restrict__ node) {
    int i = blockIdx.x * blockDim.x + threadIdx.x;
    if (i >= NN * DIM) return;
    int n = i >> 6;      // /64
    int c = i & 63;
    node[i] = emb[types[n] * DIM + c];
}

// eh(d) table per layer: sp2(sp2(rbf(d)@cf1 + b1)@cf2 + b2)
__global__ void build_table_kernel(const float* __restrict__ cf1_w,  // [3,5,64]
                                   const float* __restrict__ cf1_b,  // [3,64]
                                   const float* __restrict__ cf2_w,  // [3,64,64]
                                   const float* __restrict__ cf2_b,  // [3,64]
                                   float* __restrict__ table) {
    __shared__ float h[DIM];
    int b = blockIdx.x;
    int layer = b / TABLE_N;
    int ent   = b % TABLE_N;
    int j = threadIdx.x;

    const float gap = CUTOFF / 4.0f;                 // linspace(0,5,5) gap = 1.25
    float d = (float)ent * (CUTOFF / (float)(TABLE_N - 1));

    float rbf[5];
#pragma unroll
    for (int r = 0; r < 5; r++) {
        float t = d - (float)r * gap;
        rbf[r] = expf(-(1.0f / gap) * t * t);
    }
    float acc = cf1_b[layer * DIM + j];
#pragma unroll
    for (int r = 0; r < 5; r++)
        acc += rbf[r] * cf1_w[(layer * 5 + r) * DIM + j];
    h[j] = sp2f(acc);
    __syncthreads();

    float acc2 = cf2_b[layer * DIM + j];
    const float* W = cf2_w + layer * DIM * DIM;
#pragma unroll 8
    for (int k = 0; k < DIM; k++)
        acc2 += h[k] * W[k * DIM + j];
    table[(layer * TABLE_N + ent) * DIM + j] = sp2f(acc2);
}

// one warp per edge; each lane handles 2 consecutive floats (float2)
__global__ void edge_kernel(const int* __restrict__ src,
                            const int* __restrict__ dst,
                            const float* __restrict__ dist,
                            const float* __restrict__ newnode,
                            const float* __restrict__ table,   // [TABLE_N,64]
                            float* __restrict__ agg) {
    int idx = blockIdx.x * blockDim.x + threadIdx.x;
    int e = idx >> 5;
    if (e >= NE) return;
    int lane = idx & 31;

    int s = __ldg(src + e);
    int t = __ldg(dst + e);
    float dd = __ldg(dist + e);

    float f = dd * ((float)(TABLE_N - 1) / CUTOFF);
    f = fminf(fmaxf(f, 0.0f), (float)(TABLE_N - 1));
    int i0 = (int)f;
    if (i0 > TABLE_N - 2) i0 = TABLE_N - 2;
    float fr = f - (float)i0;

    const float2* nn = (const float2*)(newnode + (size_t)s * DIM);
    const float2* t0 = (const float2*)(table + (size_t)i0 * DIM);
    const float2* t1 = (const float2*)(table + (size_t)(i0 + 1) * DIM);

    float2 a  = nn[lane];
    float2 u0 = t0[lane];
    float2 u1 = t1[lane];
    float mx = a.x * (u0.x + fr * (u1.x - u0.x));
    float my = a.y * (u0.y + fr * (u1.y - u0.y));

    float* out = agg + (size_t)t * DIM + lane * 2;
    asm volatile("red.global.add.v2.f32 [%0], {%1, %2};"
                 :: "l"(out), "f"(mx), "f"(my) : "memory");
}

// graph pooling: accumulate res rows into per-graph sums
__global__ void pool_kernel(const int* __restrict__ gid,
                            const float* __restrict__ res,
                            float* __restrict__ gsum) {
    int idx = blockIdx.x * blockDim.x + threadIdx.x;   // NN * 128 threads
    if (idx >= NN * (HID / 2)) return;
    int n  = idx >> 7;        // /128
    int c2 = idx & 127;
    int g = __ldg(gid + n);
    const float2 v = ((const float2*)(res + (size_t)n * HID))[c2];
    float* out = gsum + (size_t)g * HID + c2 * 2;
    asm volatile("red.global.add.v2.f32 [%0], {%1, %2};"
                 :: "l"(out), "f"(v.x), "f"(v.y) : "memory");
}

__global__ void count_kernel(const int* __restrict__ gid, float* __restrict__ gcnt) {
    int i = blockIdx.x * blockDim.x + threadIdx.x;
    if (i < NN) atomicAdd(&gcnt[gid[i]], 1.0f);
}

__global__ void mean_kernel(const float* __restrict__ gsum,
                            const float* __restrict__ gcnt,
                            float* __restrict__ gmean) {
    int i = blockIdx.x * blockDim.x + threadIdx.x;
    if (i >= NG * HID) return;
    int g = i >> 8;   // /256
    gmean[i] = gsum[i] / fmaxf(gcnt[g], 1.0f);
}

// ---------------- SGEMM: f32x2, dup-B smem, KC=32 chunks --------------------
// C = act(A@B + bias) [+C].  A:[M,K] rm, B:[K,N] rm.
// BM=128, BN=64, KC=32, 256 threads. Thread (tr=tid>>3, tc=tid&7):
//   rows row0 = tr*4 (as 2 f32x2 row-pairs), cols col(c) = (c>>1)*16 + tc*2 + (c&1).
// Inner loop: 1 LDS.128 (A rows) + 4 LDS.128 (dup'd B) + 16 FFMA2 — no MOVs,
// conflict-free (contiguous 64B/128B warp accesses).
#define BM 128
#define BN 64
#define KC 32

__global__ __launch_bounds__(256)
void sgemm_kernel(const float* __restrict__ A,
                  const float* __restrict__ B,
                  const float* __restrict__ bias,
                  float* __restrict__ C,
                  int M, int N, int K, int act, int flags) {
    __shared__ float As[KC][BM];        // 16 KB, k-major
    __shared__ float Bd[KC][BN * 2];    // 16 KB, duplicated: Bd[k][2n]=Bd[k][2n+1]=B[k][n]

    int bm = blockIdx.y * BM;
    int bn = blockIdx.x * BN;
    int tid = threadIdx.x;
    int tr = tid >> 3;             // 0..31
    int tc = tid & 7;              // 0..7
    int row0 = tr * 4;

    uint64_t acc[2][8];            // [row-pair][col]; pair = rows (row0+2rp, row0+2rp+1)
#pragma unroll
    for (int i = 0; i < 2; i++)
#pragma unroll
        for (int j = 0; j < 8; j++) acc[i][j] = 0ull;

    const bool reluA = (flags & FLAG_RELUA) != 0;

    for (int k0 = 0; k0 < K; k0 += KC) {
        // ---- load A chunk (BM x KC = 4096 floats): 4 float4 per thread ----
#pragma unroll
        for (int q = 0; q < 4; q++) {
            int lin = tid * 4 + q;          // 0..1023 float4 slots
            int m   = lin >> 3;             // 0..127
            int ks  = (lin & 7) * 4;        // 0,4,...,28
            int gr  = bm + m;
            float4 v = make_float4(0.f, 0.f, 0.f, 0.f);
            if (gr < M)
                v = *(const float4*)(A + (size_t)gr * K + k0 + ks);
            if (reluA) {
                v.x = fmaxf(v.x, 0.f); v.y = fmaxf(v.y, 0.f);
                v.z = fmaxf(v.z, 0.f); v.w = fmaxf(v.w, 0.f);
            }
            As[ks + 0][m] = v.x;
            As[ks + 1][m] = v.y;
            As[ks + 2][m] = v.z;
            As[ks + 3][m] = v.w;
        }
        // ---- load B chunk duplicated (KC x BN src): 8 floats per thread ----
        {
            int kk = tid >> 3;              // 0..31
            int n0 = (tid & 7) * 8;         // 0,8,...,56
            const float* Brow = B + (size_t)(k0 + kk) * N + bn;
#pragma unroll
            for (int p = 0; p < 4; p++) {
                int n = n0 + p * 2;
                float x = 0.f, y = 0.f;
                int gc = bn + n;
                if (gc + 1 < N) {
                    float2 v2 = *(const float2*)(Brow + n);
                    x = v2.x; y = v2.y;
                } else {
                    if (gc < N) x = Brow[n];
                }
                *(uint64_t*)&Bd[kk][2 * n]     = dup2(x);
                *(uint64_t*)&Bd[kk][2 * n + 2] = dup2(y);
            }
        }
        __syncthreads();

#pragma unroll
        for (int kk = 0; kk < KC; kk++) {
            float4 av = *(const float4*)&As[kk][row0];
            uint64_t ap0 = pack2(av.x, av.y);     // rows (row0, row0+1) — reg alias
            uint64_t ap1 = pack2(av.z, av.w);     // rows (row0+2, row0+3)
            uint64_t b[8];
#pragma unroll
            for (int j = 0; j < 4; j++) {
                float4 bv = *(const float4*)&Bd[kk][j * 32 + tc * 4];
                b[j * 2]     = pack2(bv.x, bv.y); // dup'd col j*16+tc*2
                b[j * 2 + 1] = pack2(bv.z, bv.w); // dup'd col j*16+tc*2+1
            }
#pragma unroll
            for (int c = 0; c < 8; c++) {
                ffma2(acc[0][c], ap0, b[c]);
                ffma2(acc[1][c], ap1, b[c]);
            }
        }
        __syncthreads();
    }

    // ---- epilogue: 4 rows x 8 cols; cols grouped as 4 adjacent pairs ----
#pragma unroll
    for (int rp = 0; rp < 2; rp++) {
#pragma unroll
        for (int h = 0; h < 2; h++) {
            int r = bm + row0 + rp * 2 + h;
            if (r >= M) continue;
            float vals[8];
#pragma unroll
            for (int c = 0; c < 8; c++) {
                float lo, hi;
                unpack2(acc[rp][c], lo, hi);
                vals[c] = h ? hi : lo;
            }
#pragma unroll
            for (int j = 0; j < 4; j++) {        // adjacent col pair per group
                int c0 = bn + j * 16 + tc * 2;
#pragma unroll
                for (int u = 0; u < 2; u++) {
                    int c = c0 + u;
                    if (c >= N) continue;
                    float v = vals[j * 2 + u];
                    if (bias) v += bias[c];
                    if (act == 1) v = sp2f(v);
                    else if (act == 2) v = sspf(v);
                    if (flags & FLAG_BETA) v += C[(size_t)r * N + c];
                    C[(size_t)r * N + c] = v;
                }
            }
        }
    }
}

// ---------------- driver ----------------------------------------------------
static inline dim3 gemm_grid(int M, int N) {
    return dim3((N + BN - 1) / BN, (M + BM - 1) / BM);
}

extern "C" void kernel_launch(void* const* d_in, const int* in_sizes, int n_in,
                              void* d_out, int out_size) {
    const int*   node_types = (const int*)  d_in[0];
    const int*   edge_src   = (const int*)  d_in[1];
    const int*   edge_dst   = (const int*)  d_in[2];
    const int*   graph_ids  = (const int*)  d_in[3];
    const float* distance   = (const float*)d_in[4];
    const float* emb        = (const float*)d_in[5];
    const float* conv_w1    = (const float*)d_in[6];
    const float* cf1_w      = (const float*)d_in[7];
    const float* cf1_b      = (const float*)d_in[8];
    const float* cf2_w      = (const float*)d_in[9];
    const float* cf2_b      = (const float*)d_in[10];
    const float* nl2_w      = (const float*)d_in[11];
    const float* nl2_b      = (const float*)d_in[12];
    const float* nl3_w      = (const float*)d_in[13];
    const float* nl3_b      = (const float*)d_in[14];
    const float* d1_w       = (const float*)d_in[15];
    const float* d1_b       = (const float*)d_in[16];
    const float* d2_w       = (const float*)d_in[17];
    const float* d2_b       = (const float*)d_in[18];
    const float* cls_w      = (const float*)d_in[19];
    const float* cls_b      = (const float*)d_in[20];
    const float* ac_w       = (const float*)d_in[21];
    const float* ac_b       = (const float*)d_in[22];
    float* out = (float*)d_out;

    float *node, *newnode, *agg, *atom, *res, *table, *gsum, *gcnt, *gmean;
    cudaGetSymbolAddress((void**)&node,    g_node);
    cudaGetSymbolAddress((void**)&newnode, g_newnode);
    cudaGetSymbolAddress((void**)&agg,     g_agg);
    cudaGetSymbolAddress((void**)&atom,    g_atom);
    cudaGetSymbolAddress((void**)&res,     g_res);
    cudaGetSymbolAddress((void**)&table,   g_table);
    cudaGetSymbolAddress((void**)&gsum,    g_gsum);
    cudaGetSymbolAddress((void**)&gcnt,    g_gcnt);
    cudaGetSymbolAddress((void**)&gmean,   g_gmean);

    // node = emb[node_types]
    embed_kernel<<<(NN * DIM + 255) / 256, 256>>>(node_types, emb, node);

    // per-layer eh(d) lookup tables
    build_table_kernel<<<3 * TABLE_N, DIM>>>(cf1_w, cf1_b, cf2_w, cf2_b, table);

    dim3 g64 = gemm_grid(NN, DIM);
    for (int l = 0; l < 3; l++) {
        // newnode = node @ w1
        sgemm_kernel<<<g64, 256>>>(node, conv_w1 + (size_t)l * DIM * DIM,
                                   nullptr, newnode, NN, DIM, DIM, 0, 0);
        // agg = 0
        zero_kernel<<<(NN * DIM + 255) / 256, 256>>>(agg, NN * DIM);
        // agg[dst] += newnode[src] * eh(d)
        edge_kernel<<<(NE * 32 + 255) / 256, 256>>>(
            edge_src, edge_dst, distance, newnode,
            table + (size_t)l * TABLE_N * DIM, agg);
        // t = sp2(agg @ nl2 + b2)   (reuse newnode as t)
        sgemm_kernel<<<g64, 256>>>(agg, nl2_w + (size_t)l * DIM * DIM,
                                   nl2_b + l * DIM, newnode, NN, DIM, DIM, 1, 0);
        // node += t @ nl3 + b3
        sgemm_kernel<<<g64, 256>>>(newnode, nl3_w + (size_t)l * DIM * DIM,
                                   nl3_b + l * DIM, node, NN, DIM, DIM, 0, FLAG_BETA);
    }

    // atom = ssp(node @ d1 + b)
    sgemm_kernel<<<gemm_grid(NN, HID), 256>>>(node, d1_w, d1_b, atom,
                                              NN, HID, DIM, 2, 0);
    // res = atom @ d2 + b
    sgemm_kernel<<<gemm_grid(NN, HID), 256>>>(atom, d2_w, d2_b, res,
                                              NN, HID, HID, 0, 0);
    // atoms_preds = relu(res) @ ac + b   -> out[0 : NN*100]
    sgemm_kernel<<<gemm_grid(NN, NAT), 256>>>(res, ac_w, ac_b, out,
                                              NN, NAT, HID, 0, FLAG_RELUA);

    // graph pooling
    zero_kernel<<<(NG * HID + 255) / 256, 256>>>(gsum, NG * HID);
    zero_kernel<<<(NG + 255) / 256, 256>>>(gcnt, NG);
    pool_kernel<<<(NN * (HID / 2) + 255) / 256, 256>>>(graph_ids, res, gsum);
    count_kernel<<<(NN + 255) / 256, 256>>>(graph_ids, gcnt);
    mean_kernel<<<(NG * HID + 255) / 256, 256>>>(gsum, gcnt, gmean);

    // cls_preds = gmean @ cls_w + b -> out[NN*100 : ]
    sgemm_kernel<<<gemm_grid(NG, NCLS), 256>>>(gmean, cls_w, cls_b,
                                               out + (size_t)NN * NAT,
                                               NG, NCLS, HID, 0, 0);
}